// round 2
// baseline (speedup 1.0000x reference)
#include <cuda_runtime.h>
#include <cstdint>

// Problem constants
#define B_   8
#define N_   2048
#define D_   1024
#define E_   64
#define CAP_ 80
#define TOK_ (B_ * N_)              // 16384
#define OUTSZ_ 83886080ULL          // B*N*E*CAP

// ---------------- scratch (device globals; no allocation) ----------------
__device__ int   g_idx1[TOK_];
__device__ int   g_idx2[TOK_];
__device__ float g_g1[TOK_];
__device__ float g_g2[TOK_];
__device__ int   g_keep2[TOK_];
__device__ int   g_pos1[TOK_];
__device__ int   g_pos2[TOK_];
__device__ int   g_m1[TOK_];
__device__ int   g_m2[TOK_];
__device__ float g_proxy[B_ * E_];   // sum over tokens of raw gate probs, per (b,e)
__device__ int   g_count1[B_ * E_];  // pre-capacity argmax counts, per (b,e)

// ---------------- K0: zero the small accumulators ----------------
__global__ void k_zero_accum() {
    int i = threadIdx.x;
    if (i < B_ * E_) { g_proxy[i] = 0.0f; g_count1[i] = 0; }
}

// ---------------- K1: fused GEMM + softmax + top2 + gates ----------------
// Block = 256 threads, handles 64 consecutive tokens (one batch, 2048%64==0).
// GEMM tile: 64 tokens x 64 experts, K=1024 in 16 chunks of 64.
// Thread tile: 4 tokens x 4 experts (16x16 thread grid).
__global__ __launch_bounds__(256) void k_gate(
    const float* __restrict__ x,
    const float* __restrict__ w,
    const float* __restrict__ noise)
{
    __shared__ float As[64][68];   // x tile [token][k] (padded) ; reused as logitsT [e][token]
    __shared__ float Ws[64][64];   // w tile [k][expert]
    __shared__ float s_inv[64];
    __shared__ int   s_hist[64];
    __shared__ float s_red[256];

    const int tid = threadIdx.x;
    const int gt0 = blockIdx.x * 64;
    const float* xblk = x + (size_t)gt0 * D_;

    const int ty = tid >> 4;      // 0..15 (token group)
    const int tx = tid & 15;      // 0..15 (expert group)

    float acc[4][4];
    #pragma unroll
    for (int i = 0; i < 4; ++i)
        #pragma unroll
        for (int j = 0; j < 4; ++j) acc[i][j] = 0.0f;

    for (int kc = 0; kc < 16; ++kc) {
        // load x tile: 64 rows x 64 k, as float4 (1024 float4 / 256 thr = 4 each)
        #pragma unroll
        for (int i = 0; i < 4; ++i) {
            int idx = tid + i * 256;
            int r = idx >> 4, c4 = idx & 15;
            float4 v = *(const float4*)(xblk + (size_t)r * D_ + kc * 64 + c4 * 4);
            *(float4*)&As[r][c4 * 4] = v;
        }
        // load w tile: rows k = kc*64 + r
        #pragma unroll
        for (int i = 0; i < 4; ++i) {
            int idx = tid + i * 256;
            int r = idx >> 4, c4 = idx & 15;
            float4 v = *(const float4*)(w + (size_t)(kc * 64 + r) * E_ + c4 * 4);
            *(float4*)&Ws[r][c4 * 4] = v;
        }
        __syncthreads();

        #pragma unroll 8
        for (int k = 0; k < 64; ++k) {
            float4 bv = *(const float4*)&Ws[k][tx * 4];
            float a0 = As[ty * 4 + 0][k];
            float a1 = As[ty * 4 + 1][k];
            float a2 = As[ty * 4 + 2][k];
            float a3 = As[ty * 4 + 3][k];
            acc[0][0] += a0 * bv.x; acc[0][1] += a0 * bv.y; acc[0][2] += a0 * bv.z; acc[0][3] += a0 * bv.w;
            acc[1][0] += a1 * bv.x; acc[1][1] += a1 * bv.y; acc[1][2] += a1 * bv.z; acc[1][3] += a1 * bv.w;
            acc[2][0] += a2 * bv.x; acc[2][1] += a2 * bv.y; acc[2][2] += a2 * bv.z; acc[2][3] += a2 * bv.w;
            acc[3][0] += a3 * bv.x; acc[3][1] += a3 * bv.y; acc[3][2] += a3 * bv.z; acc[3][3] += a3 * bv.w;
        }
        __syncthreads();
    }

    // store logits TRANSPOSED into As: As[expert][token]  (conflict-free column reads)
    #pragma unroll
    for (int i = 0; i < 4; ++i)
        #pragma unroll
        for (int j = 0; j < 4; ++j)
            As[tx * 4 + j][ty * 4 + i] = acc[i][j];
    if (tid < 64) s_hist[tid] = 0;
    __syncthreads();

    // per-token pass: threads 0..63, token r = tid
    if (tid < 64) {
        const int r = tid;
        float m1 = -1e30f, m2 = -1e30f;
        int i1 = 0, i2 = 0;
        #pragma unroll 8
        for (int e = 0; e < 64; ++e) {
            float l = As[e][r];
            if (l > m1) { m2 = m1; i2 = i1; m1 = l; i1 = e; }
            else if (l > m2) { m2 = l; i2 = e; }
        }
        float s = 0.0f;
        #pragma unroll 8
        for (int e = 0; e < 64; ++e) {
            float p = expf(As[e][r] - m1);
            As[e][r] = p;          // stash unnormalized probs for loss pass
            s += p;
        }
        float inv = 1.0f / s;
        float g1 = inv;                       // exp(0)/sum
        float g2 = expf(m2 - m1) * inv;
        float den = g1 + g2 + 1e-9f;
        g1 /= den; g2 /= den;

        int gt = gt0 + r;
        int keep = (noise[gt] < (g2 / 0.2f)) ? 1 : 0;   // division matches reference rounding
        g_idx1[gt] = i1; g_idx2[gt] = i2;
        g_g1[gt] = g1;  g_g2[gt] = g2;
        g_keep2[gt] = keep;
        s_inv[r] = inv;
        atomicAdd(&s_hist[i1], 1);
    }
    __syncthreads();

    // loss proxy: per-expert sum of normalized probs over this block's 64 tokens
    {
        int e = tid & 63, grp = tid >> 6;      // 4 groups of 16 tokens
        float ps = 0.0f;
        int r0 = grp * 16;
        #pragma unroll
        for (int r = r0; r < r0 + 16; ++r) ps += As[e][r] * s_inv[r];
        s_red[tid] = ps;
        __syncthreads();
        if (tid < 64) {
            float v = s_red[tid] + s_red[tid + 64] + s_red[tid + 128] + s_red[tid + 192];
            int b = gt0 >> 11;
            atomicAdd(&g_proxy[b * E_ + tid], v);
            atomicAdd(&g_count1[b * E_ + tid], s_hist[tid]);
        }
    }
}

// ---------------- K2: per-batch capacity scan ----------------
// grid = B_ blocks, 64 threads; thread e owns expert e, serial scan over tokens.
__global__ __launch_bounds__(64) void k_scan() {
    const int b = blockIdx.x;
    const int e = threadIdx.x;
    const int base = b * N_;

    int cnt = 0;
    #pragma unroll 4
    for (int t = 0; t < N_; ++t) {
        int i1 = g_idx1[base + t];          // broadcast load (same addr all threads)
        if (i1 == e) {
            g_pos1[base + t] = cnt;
            g_m1[base + t] = (cnt < CAP_) ? 1 : 0;
            ++cnt;
        }
    }
    int c1t = cnt < CAP_ ? cnt : CAP_;      // post-capacity count (offset for second expert)

    int cnt2 = 0;
    #pragma unroll 4
    for (int t = 0; t < N_; ++t) {
        int i2 = g_idx2[base + t];
        if (i2 == e) {
            if (g_keep2[base + t]) {
                int p = cnt2 + c1t;
                g_pos2[base + t] = p;
                g_m2[base + t] = (p < CAP_) ? 1 : 0;
                ++cnt2;
            } else {
                g_pos2[base + t] = 0;
                g_m2[base + t] = 0;
            }
        }
    }
}

// ---------------- K3: sparse scatter + loss ----------------
__global__ __launch_bounds__(256) void k_scatter(float* __restrict__ out) {
    const int t = blockIdx.x * 256 + threadIdx.x;   // global token id == b*N + n
    float* __restrict__ comb = out + OUTSZ_;
    if (t < TOK_) {
        if (g_m1[t]) {
            size_t c = ((size_t)t * E_ + (size_t)g_idx1[t]) * CAP_ + (size_t)g_pos1[t];
            float v = g_g1[t];
            comb[c] = v;
            out[c]  = (v > 0.0f) ? 1.0f : 0.0f;
        }
        if (g_m2[t]) {
            size_t c = ((size_t)t * E_ + (size_t)g_idx2[t]) * CAP_ + (size_t)g_pos2[t];
            float v = g_g2[t];
            comb[c] = v;
            out[c]  = (v > 0.0f) ? 1.0f : 0.0f;
        }
    }
    // loss reduction in block 0
    if (blockIdx.x == 0) {
        __shared__ float red[256];
        float a = 0.0f;
        for (int i = threadIdx.x; i < B_ * E_; i += 256)
            a += g_proxy[i] * (float)g_count1[i];
        red[threadIdx.x] = a;
        __syncthreads();
        for (int s = 128; s > 0; s >>= 1) {
            if (threadIdx.x < s) red[threadIdx.x] += red[threadIdx.x + s];
            __syncthreads();
        }
        if (threadIdx.x == 0) {
            // loss = sum(proxy_sum*count)/(n*n) * e/b
            out[2 * OUTSZ_] = red[0] * ((float)E_ / ((float)B_ * (float)N_ * (float)N_));
        }
    }
}

extern "C" void kernel_launch(void* const* d_in, const int* in_sizes, int n_in,
                              void* d_out, int out_size) {
    const float* x     = (const float*)d_in[0];
    const float* w     = (const float*)d_in[1];
    const float* noise = (const float*)d_in[2];
    float* out = (float*)d_out;

    k_zero_accum<<<1, 512>>>();
    k_gate<<<TOK_ / 64, 256>>>(x, w, noise);
    k_scan<<<B_, 64>>>();
    cudaMemsetAsync(d_out, 0, (size_t)out_size * sizeof(float), 0);
    k_scatter<<<TOK_ / 256, 256>>>(out);
}

// round 5
// speedup vs baseline: 1.6946x; 1.6946x over previous
#include <cuda_runtime.h>
#include <cstdint>

#define B_    8
#define N_    2048
#define D_    1024
#define E_    64
#define CAP_  80
#define TOK_  (B_ * N_)                 // 16384
#define TPB_  128                       // tokens per gate block / chunk
#define NCHUNK_ (TOK_ / TPB_)           // 128 chunks (16 per batch)
#define OUTSZ_ 83886080ULL              // B*N*E*CAP
#define S_AS  65                        // As row stride (odd -> conflict-free columns)

// ---------------- scratch (device globals) ----------------
__device__ int   g_meta[TOK_];          // idx1 | idx2<<6 | keep<<12
__device__ float g_g1[TOK_];
__device__ float g_g2[TOK_];
__device__ int   g_p1[TOK_];            // capacity position or -1
__device__ int   g_p2[TOK_];
__device__ int   g_hist1[NCHUNK_ * E_];
__device__ int   g_hist2[NCHUNK_ * E_];
__device__ float g_proxyp[NCHUNK_ * E_];
__device__ int   g_off1[NCHUNK_ * E_];
__device__ int   g_off2[NCHUNK_ * E_];
__device__ float g_loss;

// ---------------- K1: fused GEMM(f32x2) + softmax + top2 + hists ----------------
// 128 threads, 128 tokens/block. Thread tile: 8 tokens x 8 experts (4 f32x2 pairs).
extern __shared__ float dynsh[];

__global__ __launch_bounds__(TPB_) void k_gate(
    const float* __restrict__ x,
    const float* __restrict__ w,
    const float* __restrict__ noise)
{
    float* As = dynsh;                       // [128][S_AS] x-tile, later probs[t][e]
    float* Ws = dynsh + 128 * S_AS;          // [64][64]
    __shared__ float s_inv[TPB_];
    __shared__ int   s_i1[TPB_];
    __shared__ int   s_i2[TPB_];             // -1 if not kept

    const int tid = threadIdx.x;
    const int ty  = tid >> 3;                // 0..15 token group
    const int tx  = tid & 7;                 // 0..7 expert group
    const int t0  = ty * 8;
    const int gt0 = blockIdx.x * TPB_;
    const float* xblk = x + (size_t)gt0 * D_;

    unsigned long long acc[8][4];
    #pragma unroll
    for (int i = 0; i < 8; ++i)
        #pragma unroll
        for (int j = 0; j < 4; ++j) acc[i][j] = 0ULL;

    for (int kc = 0; kc < 16; ++kc) {
        // x tile: 128 tokens x 64 k = 2048 float4 loads, scalar STS (stride 65!)
        #pragma unroll
        for (int i = 0; i < 16; ++i) {
            int idx = tid + i * TPB_;
            int r = idx >> 4, c4 = idx & 15;
            float4 v = *(const float4*)(xblk + (size_t)r * D_ + kc * 64 + c4 * 4);
            float* p = &As[r * S_AS + c4 * 4];
            p[0] = v.x; p[1] = v.y; p[2] = v.z; p[3] = v.w;
        }
        // w tile: 64 k x 64 e = 1024 float4 (stride 64 -> aligned STS.128)
        #pragma unroll
        for (int i = 0; i < 8; ++i) {
            int idx = tid + i * TPB_;
            int kr = idx >> 4, c4 = idx & 15;
            float4 v = *(const float4*)(w + (size_t)(kc * 64 + kr) * E_ + c4 * 4);
            *(float4*)&Ws[kr * 64 + c4 * 4] = v;
        }
        __syncthreads();

        #pragma unroll 8
        for (int k = 0; k < 64; ++k) {
            unsigned long long a2[8], w2[4];
            #pragma unroll
            for (int i = 0; i < 8; ++i) {
                float a = As[(t0 + i) * S_AS + k];
                asm("mov.b64 %0, {%1, %1};" : "=l"(a2[i]) : "f"(a));
            }
            #pragma unroll
            for (int j = 0; j < 4; ++j)
                w2[j] = *(const unsigned long long*)&Ws[k * 64 + 2 * tx + 16 * j];
            #pragma unroll
            for (int i = 0; i < 8; ++i)
                #pragma unroll
                for (int j = 0; j < 4; ++j)
                    asm("fma.rn.f32x2 %0, %1, %2, %0;" : "+l"(acc[i][j]) : "l"(a2[i]), "l"(w2[j]));
        }
        __syncthreads();
    }

    // write logits into As[t][e]   (e = 2*tx + 16*j + m)
    #pragma unroll
    for (int i = 0; i < 8; ++i)
        #pragma unroll
        for (int j = 0; j < 4; ++j) {
            float lo, hi;
            asm("mov.b64 {%0, %1}, %2;" : "=f"(lo), "=f"(hi) : "l"(acc[i][j]));
            As[(t0 + i) * S_AS + 2 * tx + 16 * j]     = lo;
            As[(t0 + i) * S_AS + 2 * tx + 16 * j + 1] = hi;
        }
    __syncthreads();

    // per-token pass: thread = token
    {
        const int t = tid;
        float m1 = -1e30f, m2 = -1e30f;
        int i1 = 0, i2 = 0;
        #pragma unroll 8
        for (int e = 0; e < E_; ++e) {
            float l = As[t * S_AS + e];
            if (l > m1) { m2 = m1; i2 = i1; m1 = l; i1 = e; }
            else if (l > m2) { m2 = l; i2 = e; }
        }
        float s = 0.0f;
        #pragma unroll 8
        for (int e = 0; e < E_; ++e) {
            float p = expf(As[t * S_AS + e] - m1);
            As[t * S_AS + e] = p;                    // unnormalized probs for loss
            s += p;
        }
        float inv = 1.0f / s;
        float g1 = inv;
        float g2 = expf(m2 - m1) * inv;
        float den = g1 + g2 + 1e-9f;
        g1 /= den; g2 /= den;

        int gt = gt0 + t;
        int keep = (noise[gt] < (g2 / 0.2f)) ? 1 : 0;
        g_meta[gt] = i1 | (i2 << 6) | (keep << 12);
        g_g1[gt] = g1; g_g2[gt] = g2;
        s_i1[t] = i1;
        s_i2[t] = keep ? i2 : -1;
        s_inv[t] = inv;
    }
    __syncthreads();

    // per-expert partials: proxy sum + hists (threads 0..63)
    if (tid < E_) {
        const int e = tid;
        float ps = 0.0f; int c1 = 0, c2 = 0;
        #pragma unroll 4
        for (int t = 0; t < TPB_; ++t) {
            ps += As[t * S_AS + e] * s_inv[t];
            c1 += (s_i1[t] == e);
            c2 += (s_i2[t] == e);
        }
        int o = blockIdx.x * E_ + e;
        g_proxyp[o] = ps;
        g_hist1[o] = c1;
        g_hist2[o] = c2;
    }
}

// ---------------- K2: chunk prefix + loss ----------------
// single block, 512 threads = (b, e) pairs
__global__ __launch_bounds__(512) void k_offsets() {
    __shared__ float red[512];
    const int tid = threadIdx.x;
    const int b = tid >> 6, e = tid & 63;
    const int cg0 = b * (NCHUNK_ / B_);      // 16 chunks per batch

    int off = 0;
    float px = 0.0f;
    #pragma unroll
    for (int c = 0; c < NCHUNK_ / B_; ++c) {
        int o = (cg0 + c) * E_ + e;
        g_off1[o] = off;
        off += g_hist1[o];
        px += g_proxyp[o];
    }
    int total1 = off;
    int c1t = total1 < CAP_ ? total1 : CAP_;

    int off2 = c1t;
    #pragma unroll
    for (int c = 0; c < NCHUNK_ / B_; ++c) {
        int o = (cg0 + c) * E_ + e;
        g_off2[o] = off2;
        off2 += g_hist2[o];
    }

    red[tid] = px * (float)total1;
    __syncthreads();
    for (int s = 256; s > 0; s >>= 1) {
        if (tid < s) red[tid] += red[tid + s];
        __syncthreads();
    }
    if (tid == 0)
        g_loss = red[0] * ((float)E_ / ((float)B_ * (float)N_ * (float)N_));
}

// ---------------- K3: per-chunk local scan ----------------
__global__ __launch_bounds__(64) void k_scanlocal() {
    __shared__ int s_meta[TPB_];
    const int chunk = blockIdx.x;
    const int e = threadIdx.x;
    const int base = chunk * TPB_;

    s_meta[e]       = g_meta[base + e];
    s_meta[e + 64]  = g_meta[base + e + 64];
    __syncthreads();

    int c1 = g_off1[chunk * E_ + e];
    int c2 = g_off2[chunk * E_ + e];
    #pragma unroll 4
    for (int t = 0; t < TPB_; ++t) {
        int m = s_meta[t];
        int i1 = m & 63;
        int i2 = (m >> 6) & 63;
        int keep = (m >> 12) & 1;
        if (i1 == e) {
            g_p1[base + t] = (c1 < CAP_) ? c1 : -1;
            ++c1;
        }
        if (i2 == e) {
            if (keep) {
                g_p2[base + t] = (c2 < CAP_) ? c2 : -1;
                ++c2;
            } else {
                g_p2[base + t] = -1;
            }
        }
    }
}

// ---------------- K4: fused zero-fill + scatter + loss ----------------
// 4 tokens per block, 256 threads. Each token row = 64*80 = 5120 floats = 1280 float4.
__global__ __launch_bounds__(256) void k_fill(float* __restrict__ out) {
    __shared__ int   so1[4], so2[4];
    __shared__ float sv1[4], sv2[4];
    const int tid = threadIdx.x;
    const int tok0 = blockIdx.x * 4;

    if (tid < 4) {
        int t = tok0 + tid;
        int m = g_meta[t];
        int p1 = g_p1[t], p2 = g_p2[t];
        so1[tid] = (p1 >= 0) ? ((m & 63) * CAP_ + p1) : -1;
        so2[tid] = (p2 >= 0) ? (((m >> 6) & 63) * CAP_ + p2) : -1;
        sv1[tid] = g_g1[t];
        sv2[tid] = g_g2[t];
    }
    __syncthreads();

    #pragma unroll
    for (int j = 0; j < 4; ++j) {
        float* __restrict__ db = out + (size_t)(tok0 + j) * 5120;
        float* __restrict__ cb = out + OUTSZ_ + (size_t)(tok0 + j) * 5120;
        const int o1 = so1[j], o2 = so2[j];
        const float v1 = sv1[j], v2 = sv2[j];
        #pragma unroll
        for (int k = 0; k < 5; ++k) {
            int q = tid + k * 256;
            int basee = q * 4;
            float4 c = make_float4(0.f, 0.f, 0.f, 0.f);
            float4 d = make_float4(0.f, 0.f, 0.f, 0.f);
            if (o1 >= basee && o1 < basee + 4) {
                ((float*)&c)[o1 - basee] = v1;
                ((float*)&d)[o1 - basee] = (v1 > 0.f) ? 1.f : 0.f;
            }
            if (o2 >= basee && o2 < basee + 4) {
                ((float*)&c)[o2 - basee] = v2;
                ((float*)&d)[o2 - basee] = (v2 > 0.f) ? 1.f : 0.f;
            }
            *(float4*)(cb + basee) = c;
            *(float4*)(db + basee) = d;
        }
    }

    if (blockIdx.x == 0 && tid == 0)
        out[2 * OUTSZ_] = g_loss;
}

extern "C" void kernel_launch(void* const* d_in, const int* in_sizes, int n_in,
                              void* d_out, int out_size) {
    const float* x     = (const float*)d_in[0];
    const float* w     = (const float*)d_in[1];
    const float* noise = (const float*)d_in[2];
    float* out = (float*)d_out;

    const int dyn = (128 * S_AS + 64 * 64) * sizeof(float);   // 49,664 B
    cudaFuncSetAttribute(k_gate, cudaFuncAttributeMaxDynamicSharedMemorySize, dyn);

    k_gate<<<NCHUNK_, TPB_, dyn>>>(x, w, noise);
    k_offsets<<<1, 512>>>();
    k_scanlocal<<<NCHUNK_, 64>>>();
    k_fill<<<TOK_ / 4, 256>>>(out);
}

// round 6
// speedup vs baseline: 2.1266x; 1.2549x over previous
#include <cuda_runtime.h>
#include <cstdint>

#define B_    8
#define N_    2048
#define D_    1024
#define E_    64
#define CAP_  80
#define TOK_  (B_ * N_)                 // 16384
#define TPB_  128                       // tokens per gate block / chunk
#define NCHUNK_ (TOK_ / TPB_)           // 128 chunks (16 per batch)
#define OUTSZ_ 83886080ULL              // B*N*E*CAP
#define S_AS  65                        // As row stride (odd -> conflict-free columns)

#define GRID_TOTAL 148
#define FILL4_     41943040             // (2*OUTSZ_)/4  total float4 to zero
#define PERBLK_    283400               // ceil(FILL4_/148)
#define PERKC_     17713                // ceil(PERBLK_/16)

// ---------------- scratch (device globals) ----------------
__device__ int   g_meta[TOK_];          // idx1 | idx2<<6 | keep<<12
__device__ float g_g1[TOK_];
__device__ float g_g2[TOK_];
__device__ int   g_hist1[NCHUNK_ * E_];
__device__ int   g_hist2[NCHUNK_ * E_];
__device__ float g_proxyp[NCHUNK_ * E_];
__device__ int   g_off1[NCHUNK_ * E_];
__device__ int   g_off2[NCHUNK_ * E_];
__device__ float g_loss;

// ---------------- K1: fused GEMM(f32x2)+softmax+top2+hists + zero-fill ----------------
// Blocks 0..127: gate work on 128 tokens + interleaved slice of output zero-fill.
// Blocks 128..147: pure zero-fill.
extern __shared__ float dynsh[];

__device__ __forceinline__ void fill_range(float4* __restrict__ o4, long lo, long hi, int tid) {
    const float4 z = make_float4(0.f, 0.f, 0.f, 0.f);
    for (long idx = lo + tid; idx < hi; idx += TPB_)
        o4[idx] = z;
}

__global__ __launch_bounds__(TPB_) void k_gatefill(
    const float* __restrict__ x,
    const float* __restrict__ w,
    const float* __restrict__ noise,
    float* __restrict__ out)
{
    const int tid = threadIdx.x;
    float4* __restrict__ o4 = (float4*)out;

    const long flo = (long)blockIdx.x * PERBLK_;
    const long fhi = (flo + PERBLK_ < (long)FILL4_) ? flo + PERBLK_ : (long)FILL4_;

    if (blockIdx.x >= NCHUNK_) {        // fill-only blocks
        fill_range(o4, flo, fhi, tid);
        return;
    }

    float* As = dynsh;                       // [128][S_AS] x-tile, later probs[t][e]
    float* Ws = dynsh + 128 * S_AS;          // [64][64]
    __shared__ float s_inv[TPB_];
    __shared__ int   s_i1[TPB_];
    __shared__ int   s_i2[TPB_];             // -1 if not kept

    const int ty  = tid >> 3;                // 0..15 token group
    const int tx  = tid & 7;                 // 0..7 expert group
    const int t0  = ty * 8;
    const int gt0 = blockIdx.x * TPB_;
    const float* xblk = x + (size_t)gt0 * D_;

    unsigned long long acc[8][4];
    #pragma unroll
    for (int i = 0; i < 8; ++i)
        #pragma unroll
        for (int j = 0; j < 4; ++j) acc[i][j] = 0ULL;

    for (int kc = 0; kc < 16; ++kc) {
        // x tile: scalar STS (stride 65 keeps columns conflict-free; float4 STS would misalign)
        #pragma unroll
        for (int i = 0; i < 16; ++i) {
            int idx = tid + i * TPB_;
            int r = idx >> 4, c4 = idx & 15;
            float4 v = *(const float4*)(xblk + (size_t)r * D_ + kc * 64 + c4 * 4);
            float* p = &As[r * S_AS + c4 * 4];
            p[0] = v.x; p[1] = v.y; p[2] = v.z; p[3] = v.w;
        }
        // w tile
        #pragma unroll
        for (int i = 0; i < 8; ++i) {
            int idx = tid + i * TPB_;
            int kr = idx >> 4, c4 = idx & 15;
            float4 v = *(const float4*)(w + (size_t)(kc * 64 + kr) * E_ + c4 * 4);
            *(float4*)&Ws[kr * 64 + c4 * 4] = v;
        }
        __syncthreads();

        #pragma unroll 8
        for (int k = 0; k < 64; ++k) {
            unsigned long long a2[8], w2[4];
            #pragma unroll
            for (int i = 0; i < 8; ++i) {
                float a = As[(t0 + i) * S_AS + k];
                asm("mov.b64 %0, {%1, %1};" : "=l"(a2[i]) : "f"(a));
            }
            #pragma unroll
            for (int j = 0; j < 4; ++j)
                w2[j] = *(const unsigned long long*)&Ws[k * 64 + 2 * tx + 16 * j];
            #pragma unroll
            for (int i = 0; i < 8; ++i)
                #pragma unroll
                for (int j = 0; j < 4; ++j)
                    asm("fma.rn.f32x2 %0, %1, %2, %0;" : "+l"(acc[i][j]) : "l"(a2[i]), "l"(w2[j]));
        }

        // interleaved zero-fill slice for this k-chunk (fire-and-forget stores)
        {
            long lo = flo + (long)kc * PERKC_;
            long hi = lo + PERKC_;
            if (hi > fhi) hi = fhi;
            if (lo < hi) fill_range(o4, lo, hi, tid);
        }
        __syncthreads();
    }

    // write logits into As[t][e]   (e = 2*tx + 16*j + m)
    #pragma unroll
    for (int i = 0; i < 8; ++i)
        #pragma unroll
        for (int j = 0; j < 4; ++j) {
            float lo, hi;
            asm("mov.b64 {%0, %1}, %2;" : "=f"(lo), "=f"(hi) : "l"(acc[i][j]));
            As[(t0 + i) * S_AS + 2 * tx + 16 * j]     = lo;
            As[(t0 + i) * S_AS + 2 * tx + 16 * j + 1] = hi;
        }
    __syncthreads();

    // per-token pass: thread = token
    {
        const int t = tid;
        float m1 = -1e30f, m2 = -1e30f;
        int i1 = 0, i2 = 0;
        #pragma unroll 8
        for (int e = 0; e < E_; ++e) {
            float l = As[t * S_AS + e];
            if (l > m1) { m2 = m1; i2 = i1; m1 = l; i1 = e; }
            else if (l > m2) { m2 = l; i2 = e; }
        }
        float s = 0.0f;
        #pragma unroll 8
        for (int e = 0; e < E_; ++e) {
            float p = expf(As[t * S_AS + e] - m1);
            As[t * S_AS + e] = p;                    // unnormalized probs for loss
            s += p;
        }
        float inv = 1.0f / s;
        float g1 = inv;
        float g2 = expf(m2 - m1) * inv;
        float den = g1 + g2 + 1e-9f;
        g1 /= den; g2 /= den;

        int gt = gt0 + t;
        int keep = (noise[gt] < (g2 / 0.2f)) ? 1 : 0;
        g_meta[gt] = i1 | (i2 << 6) | (keep << 12);
        g_g1[gt] = g1; g_g2[gt] = g2;
        s_i1[t] = i1;
        s_i2[t] = keep ? i2 : -1;
        s_inv[t] = inv;
    }
    __syncthreads();

    // per-expert partials: proxy sum + hists (threads 0..63)
    if (tid < E_) {
        const int e = tid;
        float ps = 0.0f; int c1 = 0, c2 = 0;
        #pragma unroll 4
        for (int t = 0; t < TPB_; ++t) {
            ps += As[t * S_AS + e] * s_inv[t];
            c1 += (s_i1[t] == e);
            c2 += (s_i2[t] == e);
        }
        int o = blockIdx.x * E_ + e;
        g_proxyp[o] = ps;
        g_hist1[o] = c1;
        g_hist2[o] = c2;
    }
}

// ---------------- K2: chunk prefix + loss ----------------
__global__ __launch_bounds__(512) void k_offsets() {
    __shared__ float red[512];
    const int tid = threadIdx.x;
    const int b = tid >> 6, e = tid & 63;
    const int cg0 = b * (NCHUNK_ / B_);      // 16 chunks per batch

    int off = 0;
    float px = 0.0f;
    #pragma unroll
    for (int c = 0; c < NCHUNK_ / B_; ++c) {
        int o = (cg0 + c) * E_ + e;
        g_off1[o] = off;
        off += g_hist1[o];
        px += g_proxyp[o];
    }
    int total1 = off;
    int c1t = total1 < CAP_ ? total1 : CAP_;

    int off2 = c1t;
    #pragma unroll
    for (int c = 0; c < NCHUNK_ / B_; ++c) {
        int o = (cg0 + c) * E_ + e;
        g_off2[o] = off2;
        off2 += g_hist2[o];
    }

    red[tid] = px * (float)total1;
    __syncthreads();
    for (int s = 256; s > 0; s >>= 1) {
        if (tid < s) red[tid] += red[tid + s];
        __syncthreads();
    }
    if (tid == 0)
        g_loss = red[0] * ((float)E_ / ((float)B_ * (float)N_ * (float)N_));
}

// ---------------- K3: fused local scan + sparse scatter ----------------
__global__ __launch_bounds__(64) void k_scanscatter(float* __restrict__ out) {
    __shared__ int s_meta[TPB_];
    __shared__ int sp1[TPB_];
    __shared__ int sp2[TPB_];
    const int chunk = blockIdx.x;
    const int e = threadIdx.x;
    const int base = chunk * TPB_;

    s_meta[e]      = g_meta[base + e];
    s_meta[e + 64] = g_meta[base + e + 64];
    __syncthreads();

    int c1 = g_off1[chunk * E_ + e];
    int c2 = g_off2[chunk * E_ + e];
    #pragma unroll 4
    for (int t = 0; t < TPB_; ++t) {
        int m = s_meta[t];
        int i1 = m & 63;
        int i2 = (m >> 6) & 63;
        int keep = (m >> 12) & 1;
        if (i1 == e) { sp1[t] = (c1 < CAP_) ? c1 : -1; ++c1; }
        if (i2 == e) {
            if (keep) { sp2[t] = (c2 < CAP_) ? c2 : -1; ++c2; }
            else        sp2[t] = -1;
        }
    }
    __syncthreads();

    // scatter: each thread patches 2 tokens
    #pragma unroll
    for (int q = 0; q < 2; ++q) {
        int t = e + q * 64;
        int gt = base + t;
        int m = s_meta[t];
        int p1 = sp1[t], p2 = sp2[t];
        float* db = out + (size_t)gt * (E_ * CAP_);
        float* cb = out + OUTSZ_ + (size_t)gt * (E_ * CAP_);
        if (p1 >= 0) {
            int o = (m & 63) * CAP_ + p1;
            float v = g_g1[gt];
            cb[o] = v;
            db[o] = (v > 0.f) ? 1.f : 0.f;
        }
        if (p2 >= 0) {
            int o = ((m >> 6) & 63) * CAP_ + p2;
            float v = g_g2[gt];
            cb[o] = v;
            db[o] = (v > 0.f) ? 1.f : 0.f;
        }
    }

    if (chunk == 0 && e == 0)
        out[2 * OUTSZ_] = g_loss;
}

extern "C" void kernel_launch(void* const* d_in, const int* in_sizes, int n_in,
                              void* d_out, int out_size) {
    const float* x     = (const float*)d_in[0];
    const float* w     = (const float*)d_in[1];
    const float* noise = (const float*)d_in[2];
    float* out = (float*)d_out;

    const int dyn = (128 * S_AS + 64 * 64) * sizeof(float);   // 49,664 B
    cudaFuncSetAttribute(k_gatefill, cudaFuncAttributeMaxDynamicSharedMemorySize, dyn);

    k_gatefill<<<GRID_TOTAL, TPB_, dyn>>>(x, w, noise, out);
    k_offsets<<<1, 512>>>();
    k_scanscatter<<<NCHUNK_, 64>>>(out);
}

// round 8
// speedup vs baseline: 2.3546x; 1.1072x over previous
#include <cuda_runtime.h>
#include <cstdint>

#define B_    8
#define N_    2048
#define D_    1024
#define E_    64
#define CAP_  80
#define TOK_  (B_ * N_)                 // 16384
#define TPB_  128                       // tokens per gate block / chunk
#define NCHUNK_ (TOK_ / TPB_)           // 128 chunks (16 per batch)
#define OUTSZ_ 83886080ULL              // B*N*E*CAP
#define S_AS  65                        // As row stride (odd -> conflict-free columns)

#define GRID_TOTAL 148
#define FILL4_     41943040             // (2*OUTSZ_)/4  total float4 to zero
#define PERBLK_    283400               // ceil(FILL4_/148)
#define PERKC_     17713                // ceil(PERBLK_/16)

// ---------------- scratch (device globals) ----------------
__device__ int   g_hist1[NCHUNK_ * E_];
__device__ int   g_hist2[NCHUNK_ * E_];
__device__ float g_proxyp[NCHUNK_ * E_];
__device__ unsigned int g_bar;          // monotonic ticket barrier (replay-safe)

extern __shared__ float dynsh[];

__device__ __forceinline__ void fill_range(float4* __restrict__ o4, long lo, long hi, int tid) {
    const float4 z = make_float4(0.f, 0.f, 0.f, 0.f);
    for (long idx = lo + tid; idx < hi; idx += TPB_)
        o4[idx] = z;
}

__device__ __forceinline__ void grid_barrier(int tid) {
    __syncthreads();
    if (tid == 0) {
        __threadfence();                                  // fills visible before scatter
        unsigned int old = atomicAdd(&g_bar, 1u);
        unsigned int target = old - (old % GRID_TOTAL) + GRID_TOTAL;
        unsigned int v;
        do {
            asm volatile("ld.acquire.gpu.u32 %0, [%1];" : "=r"(v) : "l"(&g_bar));
        } while (v < target);
    }
    __syncthreads();
}

__global__ __launch_bounds__(TPB_) void k_fused(
    const float* __restrict__ x,
    const float* __restrict__ w,
    const float* __restrict__ noise,
    float* __restrict__ out)
{
    const int tid = threadIdx.x;
    float4* __restrict__ o4 = (float4*)out;

    const long flo = (long)blockIdx.x * PERBLK_;
    const long fhi = (flo + PERBLK_ < (long)FILL4_) ? flo + PERBLK_ : (long)FILL4_;

    __shared__ int   s_meta[TPB_];       // idx1 | idx2<<6 | keep<<12
    __shared__ float s_g1[TPB_];
    __shared__ float s_g2[TPB_];
    __shared__ float s_inv[TPB_];
    __shared__ int   s_i1[TPB_];
    __shared__ int   s_i2[TPB_];
    __shared__ int   sp1[TPB_];
    __shared__ int   sp2[TPB_];

    // ================= Phase A =================
    if (blockIdx.x >= NCHUNK_) {
        fill_range(o4, flo, fhi, tid);
    } else {
        float* As = dynsh;                       // [128][S_AS]
        float* Ws = dynsh + 128 * S_AS;          // [64][64]

        const int ty  = tid >> 3;
        const int tx  = tid & 7;
        const int t0  = ty * 8;
        const int gt0 = blockIdx.x * TPB_;
        const float* xblk = x + (size_t)gt0 * D_;

        unsigned long long acc[8][4];
        #pragma unroll
        for (int i = 0; i < 8; ++i)
            #pragma unroll
            for (int j = 0; j < 4; ++j) acc[i][j] = 0ULL;

        for (int kc = 0; kc < 16; ++kc) {
            #pragma unroll
            for (int i = 0; i < 16; ++i) {
                int idx = tid + i * TPB_;
                int r = idx >> 4, c4 = idx & 15;
                float4 v = *(const float4*)(xblk + (size_t)r * D_ + kc * 64 + c4 * 4);
                float* p = &As[r * S_AS + c4 * 4];
                p[0] = v.x; p[1] = v.y; p[2] = v.z; p[3] = v.w;
            }
            #pragma unroll
            for (int i = 0; i < 8; ++i) {
                int idx = tid + i * TPB_;
                int kr = idx >> 4, c4 = idx & 15;
                float4 v = *(const float4*)(w + (size_t)(kc * 64 + kr) * E_ + c4 * 4);
                *(float4*)&Ws[kr * 64 + c4 * 4] = v;
            }
            __syncthreads();

            #pragma unroll 8
            for (int k = 0; k < 64; ++k) {
                unsigned long long a2[8], w2[4];
                #pragma unroll
                for (int i = 0; i < 8; ++i) {
                    float a = As[(t0 + i) * S_AS + k];
                    asm("mov.b64 %0, {%1, %1};" : "=l"(a2[i]) : "f"(a));
                }
                #pragma unroll
                for (int j = 0; j < 4; ++j)
                    w2[j] = *(const unsigned long long*)&Ws[k * 64 + 2 * tx + 16 * j];
                #pragma unroll
                for (int i = 0; i < 8; ++i)
                    #pragma unroll
                    for (int j = 0; j < 4; ++j)
                        asm("fma.rn.f32x2 %0, %1, %2, %0;" : "+l"(acc[i][j]) : "l"(a2[i]), "l"(w2[j]));
            }

            // interleaved zero-fill slice
            {
                long lo = flo + (long)kc * PERKC_;
                long hi = lo + PERKC_;
                if (hi > fhi) hi = fhi;
                if (lo < hi) fill_range(o4, lo, hi, tid);
            }
            __syncthreads();
        }

        // logits -> As[t][e]
        #pragma unroll
        for (int i = 0; i < 8; ++i)
            #pragma unroll
            for (int j = 0; j < 4; ++j) {
                float lo, hi;
                asm("mov.b64 {%0, %1}, %2;" : "=f"(lo), "=f"(hi) : "l"(acc[i][j]));
                As[(t0 + i) * S_AS + 2 * tx + 16 * j]     = lo;
                As[(t0 + i) * S_AS + 2 * tx + 16 * j + 1] = hi;
            }
        __syncthreads();

        // per-token: softmax + top2 + gates
        {
            const int t = tid;
            float m1 = -1e30f, m2 = -1e30f;
            int i1 = 0, i2 = 0;
            #pragma unroll 8
            for (int e = 0; e < E_; ++e) {
                float l = As[t * S_AS + e];
                if (l > m1) { m2 = m1; i2 = i1; m1 = l; i1 = e; }
                else if (l > m2) { m2 = l; i2 = e; }
            }
            float s = 0.0f;
            #pragma unroll 8
            for (int e = 0; e < E_; ++e) {
                float p = expf(As[t * S_AS + e] - m1);
                As[t * S_AS + e] = p;
                s += p;
            }
            float inv = 1.0f / s;
            float g1 = inv;
            float g2 = expf(m2 - m1) * inv;
            float den = g1 + g2 + 1e-9f;
            g1 /= den; g2 /= den;

            int keep = (noise[gt0 + t] < (g2 / 0.2f)) ? 1 : 0;
            s_meta[t] = i1 | (i2 << 6) | (keep << 12);
            s_g1[t] = g1; s_g2[t] = g2;
            s_i1[t] = i1;
            s_i2[t] = keep ? i2 : -1;
            s_inv[t] = inv;
        }
        __syncthreads();

        // per-expert partials -> global (cross-block prefix + loss need these)
        if (tid < E_) {
            const int e = tid;
            float ps = 0.0f; int c1 = 0, c2 = 0;
            #pragma unroll 4
            for (int t = 0; t < TPB_; ++t) {
                ps += As[t * S_AS + e] * s_inv[t];
                c1 += (s_i1[t] == e);
                c2 += (s_i2[t] == e);
            }
            int o = blockIdx.x * E_ + e;
            g_proxyp[o] = ps;
            g_hist1[o] = c1;
            g_hist2[o] = c2;
        }
    }

    // ================= barrier (orders fills + hists before phase B) =================
    grid_barrier(tid);

    // ================= Phase B =================
    if (blockIdx.x < NCHUNK_) {
        const int chunk = blockIdx.x;
        const int b = chunk >> 4;              // 16 chunks per batch
        const int myc = chunk & 15;
        const int cg0 = b * 16;

        if (tid < E_) {
            const int e = tid;
            // offsets for this chunk from batch histograms
            int off1 = 0, tot1 = 0, off2p = 0;
            #pragma unroll
            for (int c = 0; c < 16; ++c) {
                int h1 = g_hist1[(cg0 + c) * E_ + e];
                int h2 = g_hist2[(cg0 + c) * E_ + e];
                if (c < myc) { off1 += h1; off2p += h2; }
                tot1 += h1;
            }
            int c1t = tot1 < CAP_ ? tot1 : CAP_;
            int c1 = off1;
            int c2 = c1t + off2p;

            // local scan over this block's 128 tokens
            #pragma unroll 4
            for (int t = 0; t < TPB_; ++t) {
                int m = s_meta[t];
                int i1 = m & 63;
                int i2 = (m >> 6) & 63;
                int keep = (m >> 12) & 1;
                if (i1 == e) { sp1[t] = (c1 < CAP_) ? c1 : -1; ++c1; }
                if (i2 == e) {
                    if (keep) { sp2[t] = (c2 < CAP_) ? c2 : -1; ++c2; }
                    else        sp2[t] = -1;
                }
            }
        }
        __syncthreads();

        // scatter: thread t patches its token
        {
            const int t = tid;
            const int gt = chunk * TPB_ + t;
            int m = s_meta[t];
            int p1 = sp1[t], p2 = sp2[t];
            float* db = out + (size_t)gt * (E_ * CAP_);
            float* cb = out + OUTSZ_ + (size_t)gt * (E_ * CAP_);
            if (p1 >= 0) {
                int o = (m & 63) * CAP_ + p1;
                float v = s_g1[t];
                cb[o] = v;
                db[o] = (v > 0.f) ? 1.f : 0.f;
            }
            if (p2 >= 0) {
                int o = ((m >> 6) & 63) * CAP_ + p2;
                float v = s_g2[t];
                cb[o] = v;
                db[o] = (v > 0.f) ? 1.f : 0.f;
            }
        }
    } else if (blockIdx.x == NCHUNK_) {
        // loss: sum over (b,e) of proxyTot * total1
        __shared__ float red[64];
        if (tid < 64) {
            const int e = tid;
            float a = 0.0f;
            #pragma unroll
            for (int b = 0; b < B_; ++b) {
                float px = 0.0f; int t1 = 0;
                #pragma unroll
                for (int c = 0; c < 16; ++c) {
                    int o = (b * 16 + c) * E_ + e;
                    px += g_proxyp[o];
                    t1 += g_hist1[o];
                }
                a += px * (float)t1;
            }
            red[e] = a;
        }
        __syncthreads();
        if (tid < 32) { red[tid] += red[tid + 32]; }
        __syncwarp();
        if (tid == 0) {
            float s = 0.0f;
            #pragma unroll
            for (int i = 0; i < 32; ++i) s += red[i];
            out[2 * OUTSZ_] = s * ((float)E_ / ((float)B_ * (float)N_ * (float)N_));
        }
    }
}

extern "C" void kernel_launch(void* const* d_in, const int* in_sizes, int n_in,
                              void* d_out, int out_size) {
    const float* x     = (const float*)d_in[0];
    const float* w     = (const float*)d_in[1];
    const float* noise = (const float*)d_in[2];
    float* out = (float*)d_out;

    const int dyn = (128 * S_AS + 64 * 64) * sizeof(float);   // 49,664 B
    cudaFuncSetAttribute(k_fused, cudaFuncAttributeMaxDynamicSharedMemorySize, dyn);

    k_fused<<<GRID_TOTAL, TPB_, dyn>>>(x, w, noise, out);
}